// round 1
// baseline (speedup 1.0000x reference)
#include <cuda_runtime.h>
#include <math.h>

// Problem constants
#define Bq     16
#define Nn     1024
#define Dd     128
#define VOCABq 32000
#define HOPSq  3
#define HEADSq 4
#define KMAX   128
#define ALPHAq 0.2f
#define ROWS   (Bq * Nn)   // 16384

// ---------------- device scratch (static, allocation-free) ----------------
__device__ int   g_nbr_idx[ROWS * KMAX];          // 8 MB
__device__ int   g_nbr_cnt[ROWS];
__device__ float g_X[ROWS * Dd];                  // 8 MB  (reused per hop k)
__device__ float g_Wh[HEADSq * ROWS * Dd];        // 33.5 MB (reused per hop k)
__device__ float g_f1[HEADSq * ROWS];
__device__ float g_f2[HEADSq * ROWS];
__device__ float g_G[(HOPSq + 1) * ROWS * Dd];    // 33.5 MB
__device__ float g_u[Bq * Dd];
__device__ float g_logits[ROWS];

// ---------------- neighbor list build (once; adj & mask are hop-invariant) ----
__global__ void k_build_nbr(const float* __restrict__ adj,
                            const int* __restrict__ kb_len,
                            const int* __restrict__ conv_len) {
    int warp = (blockIdx.x * blockDim.x + threadIdx.x) >> 5;
    int lane = threadIdx.x & 31;
    if (warp >= ROWS) return;
    int b = warp / Nn, n = warp % Nn;
    int ctx = kb_len[b] + conv_len[b];
    const float* arow = adj + (size_t)warp * Nn;
    int* idx = g_nbr_idx + (size_t)warp * KMAX;
    int cnt = 0;
    for (int m0 = 0; m0 < Nn; m0 += 32) {
        int m = m0 + lane;
        bool sel = (arow[m] > 0.0f) || (m == n && n >= ctx);
        unsigned bal = __ballot_sync(0xffffffffu, sel);
        if (sel) {
            int pos = cnt + __popc(bal & ((1u << lane) - 1u));
            if (pos < KMAX) idx[pos] = m;
        }
        cnt += __popc(bal);
    }
    if (lane == 0) g_nbr_cnt[warp] = cnt < KMAX ? cnt : KMAX;
}

// ---------------- embedding + language-model add ----------------
__global__ void k_embed(const int* __restrict__ story,
                        const int* __restrict__ kb_len,
                        const int* __restrict__ conv_len,
                        const float* __restrict__ dh,
                        const float* __restrict__ emb, int hop) {
    int warp = (blockIdx.x * blockDim.x + threadIdx.x) >> 5;
    int lane = threadIdx.x & 31;
    if (warp >= ROWS) return;
    int b = warp / Nn, n = warp % Nn;
    const int* st = story + (size_t)warp * 4;
    int i0 = st[0], i1 = st[1], i2 = st[2], i3 = st[3];
    const float* E = emb + (size_t)hop * VOCABq * Dd;
    int d = lane * 4;
    float4 v0 = *(const float4*)(E + (size_t)i0 * Dd + d);
    float4 v1 = *(const float4*)(E + (size_t)i1 * Dd + d);
    float4 v2 = *(const float4*)(E + (size_t)i2 * Dd + d);
    float4 v3 = *(const float4*)(E + (size_t)i3 * Dd + d);
    float4 s;
    s.x = v0.x + v1.x + v2.x + v3.x;
    s.y = v0.y + v1.y + v2.y + v3.y;
    s.z = v0.z + v1.z + v2.z + v3.z;
    s.w = v0.w + v1.w + v2.w + v3.w;
    int rel = n - (kb_len[b] - 1);
    if (rel >= 0 && rel < conv_len[b]) {
        float4 g = *(const float4*)(dh + ((size_t)b * Nn + rel) * Dd + d);
        s.x += g.x; s.y += g.y; s.z += g.z; s.w += g.w;
    }
    *(float4*)(g_X + (size_t)warp * Dd + d) = s;
}

// ---------------- Wh = X @ W[hop][h]  (16384x128 @ 128x128, fp32) ----------------
__global__ void k_gemm_wh(const float* __restrict__ W_all, int hop) {
    int h = blockIdx.y;
    int row0 = blockIdx.x * 64;
    const float* W = W_all + (size_t)(hop * HEADSq + h) * Dd * Dd;
    __shared__ float Xs[64][36];   // padded
    __shared__ float Ws[32][128];
    int tid = threadIdx.x;
    int tx = tid & 15, ty = tid >> 4;
    float acc[4][8];
#pragma unroll
    for (int r = 0; r < 4; r++)
#pragma unroll
        for (int c = 0; c < 8; c++) acc[r][c] = 0.0f;

    for (int kt = 0; kt < Dd; kt += 32) {
#pragma unroll
        for (int s = 0; s < 2; s++) {          // 512 float4 of X tile
            int f = tid + s * 256;
            int i = f >> 3, j4 = (f & 7) * 4;
            float4 v = *(const float4*)(g_X + (size_t)(row0 + i) * Dd + kt + j4);
            Xs[i][j4 + 0] = v.x; Xs[i][j4 + 1] = v.y;
            Xs[i][j4 + 2] = v.z; Xs[i][j4 + 3] = v.w;
        }
#pragma unroll
        for (int s = 0; s < 4; s++) {          // 1024 float4 of W tile
            int f = tid + s * 256;
            int r = f >> 5, c4 = (f & 31) * 4;
            *(float4*)(&Ws[r][c4]) = *(const float4*)(W + (size_t)(kt + r) * Dd + c4);
        }
        __syncthreads();
#pragma unroll
        for (int kk = 0; kk < 32; kk++) {
            float xv[4], wv[8];
#pragma unroll
            for (int r = 0; r < 4; r++) xv[r] = Xs[ty * 4 + r][kk];
#pragma unroll
            for (int c = 0; c < 8; c++) wv[c] = Ws[kk][tx * 8 + c];
#pragma unroll
            for (int r = 0; r < 4; r++)
#pragma unroll
                for (int c = 0; c < 8; c++) acc[r][c] += xv[r] * wv[c];
        }
        __syncthreads();
    }
    float* out = g_Wh + ((size_t)h * ROWS + row0) * Dd;
#pragma unroll
    for (int r = 0; r < 4; r++) {
        float4 o0 = make_float4(acc[r][0], acc[r][1], acc[r][2], acc[r][3]);
        float4 o1 = make_float4(acc[r][4], acc[r][5], acc[r][6], acc[r][7]);
        *(float4*)(out + (size_t)(ty * 4 + r) * Dd + tx * 8)     = o0;
        *(float4*)(out + (size_t)(ty * 4 + r) * Dd + tx * 8 + 4) = o1;
    }
}

// ---------------- f1 = Wh . a[:D], f2 = Wh . a[D:] ----------------
__global__ void k_f1f2(const float* __restrict__ a_all, int hop) {
    int warp = (blockIdx.x * blockDim.x + threadIdx.x) >> 5;
    int lane = threadIdx.x & 31;
    if (warp >= HEADSq * ROWS) return;
    int h = warp / ROWS, row = warp % ROWS;
    const float* wh = g_Wh + ((size_t)h * ROWS + row) * Dd;
    const float* a  = a_all + (size_t)(hop * HEADSq + h) * 2 * Dd;
    int d = lane * 4;
    float4 v  = *(const float4*)(wh + d);
    float4 a1 = *(const float4*)(a + d);
    float4 a2 = *(const float4*)(a + Dd + d);
    float s1 = v.x * a1.x + v.y * a1.y + v.z * a1.z + v.w * a1.w;
    float s2 = v.x * a2.x + v.y * a2.y + v.z * a2.z + v.w * a2.w;
#pragma unroll
    for (int o = 16; o; o >>= 1) {
        s1 += __shfl_xor_sync(0xffffffffu, s1, o);
        s2 += __shfl_xor_sync(0xffffffffu, s2, o);
    }
    if (lane == 0) {
        g_f1[(size_t)h * ROWS + row] = s1;
        g_f2[(size_t)h * ROWS + row] = s2;
    }
}

// ---------------- sparse GAT attention -> G[hop] ----------------
__global__ void k_attn(int hop) {
    __shared__ float sw[8][HEADSq][KMAX];   // 16 KB
    int wl = threadIdx.x >> 5;
    int warp = blockIdx.x * 8 + wl;
    int lane = threadIdx.x & 31;
    if (warp >= ROWS) return;
    int b = warp / Nn;
    int cnt = g_nbr_cnt[warp];
    const int* idx = g_nbr_idx + (size_t)warp * KMAX;
    int d = lane * 4;
    float4 acc = make_float4(0.f, 0.f, 0.f, 0.f);

    if (cnt == 0) {
        // JAX softmax over all-NEG_INF row -> uniform over all m
        for (int m = 0; m < Nn; m++) {
            size_t r = ((size_t)b * Nn + m) * Dd + d;
#pragma unroll
            for (int h = 0; h < HEADSq; h++) {
                float4 v = *(const float4*)(g_Wh + (size_t)h * ROWS * Dd + r);
                acc.x += v.x; acc.y += v.y; acc.z += v.z; acc.w += v.w;
            }
        }
        float s = 1.0f / (float)(Nn * HEADSq);
        acc.x *= s; acc.y *= s; acc.z *= s; acc.w *= s;
    } else {
        float f1h[HEADSq];
#pragma unroll
        for (int h = 0; h < HEADSq; h++) f1h[h] = g_f1[(size_t)h * ROWS + warp];
        float mx[HEADSq];
#pragma unroll
        for (int h = 0; h < HEADSq; h++) mx[h] = -3.4e38f;
        for (int j = lane; j < cnt; j += 32) {
            int m = idx[j];
#pragma unroll
            for (int h = 0; h < HEADSq; h++) {
                float v = f1h[h] + g_f2[(size_t)h * ROWS + b * Nn + m];
                v = (v >= 0.0f) ? v : ALPHAq * v;
                sw[wl][h][j] = v;
                mx[h] = fmaxf(mx[h], v);
            }
        }
#pragma unroll
        for (int o = 16; o; o >>= 1)
#pragma unroll
            for (int h = 0; h < HEADSq; h++)
                mx[h] = fmaxf(mx[h], __shfl_xor_sync(0xffffffffu, mx[h], o));
        __syncwarp();
        float sum[HEADSq] = {0.f, 0.f, 0.f, 0.f};
        for (int j = lane; j < cnt; j += 32) {
#pragma unroll
            for (int h = 0; h < HEADSq; h++) {
                float w = expf(sw[wl][h][j] - mx[h]);
                sw[wl][h][j] = w;
                sum[h] += w;
            }
        }
#pragma unroll
        for (int o = 16; o; o >>= 1)
#pragma unroll
            for (int h = 0; h < HEADSq; h++)
                sum[h] += __shfl_xor_sync(0xffffffffu, sum[h], o);
        float sc[HEADSq];
#pragma unroll
        for (int h = 0; h < HEADSq; h++) sc[h] = 0.25f / sum[h];
        __syncwarp();
        for (int j = 0; j < cnt; j++) {
            int m = idx[j];
            size_t r = ((size_t)b * Nn + m) * Dd + d;
#pragma unroll
            for (int h = 0; h < HEADSq; h++) {
                float w = sw[wl][h][j] * sc[h];
                float4 v = *(const float4*)(g_Wh + (size_t)h * ROWS * Dd + r);
                acc.x += w * v.x; acc.y += w * v.y;
                acc.z += w * v.z; acc.w += w * v.w;
            }
        }
    }
    *(float4*)(g_G + ((size_t)hop * ROWS + warp) * Dd + d) = acc;
}

// ---------------- hop recurrence ----------------
__global__ void k_init_u(const float* __restrict__ hidden) {
    int i = blockIdx.x * blockDim.x + threadIdx.x;
    if (i < Bq * Dd) g_u[i] = hidden[i];
}

__global__ void k_logits(int hop) {
    int warp = (blockIdx.x * blockDim.x + threadIdx.x) >> 5;
    int lane = threadIdx.x & 31;
    if (warp >= ROWS) return;
    int b = warp / Nn;
    int d = lane * 4;
    float4 g = *(const float4*)(g_G + ((size_t)hop * ROWS + warp) * Dd + d);
    float4 u = *(const float4*)(g_u + (size_t)b * Dd + d);
    float s = g.x * u.x + g.y * u.y + g.z * u.z + g.w * u.w;
#pragma unroll
    for (int o = 16; o; o >>= 1) s += __shfl_xor_sync(0xffffffffu, s, o);
    if (lane == 0) g_logits[warp] = s;
}

__global__ void k_softmax_update(int hop) {   // uses G[hop+1]
    int b = blockIdx.x;
    int tid = threadIdx.x;                    // 512 threads
    __shared__ float red[512];
    __shared__ float p[Nn];
    const float* lg = g_logits + (size_t)b * Nn;

    float lmax = -3.4e38f;
    for (int n = tid; n < Nn; n += 512) lmax = fmaxf(lmax, lg[n]);
    red[tid] = lmax; __syncthreads();
    for (int s = 256; s; s >>= 1) { if (tid < s) red[tid] = fmaxf(red[tid], red[tid + s]); __syncthreads(); }
    float mx = red[0]; __syncthreads();

    float lsum = 0.0f;
    for (int n = tid; n < Nn; n += 512) { float w = expf(lg[n] - mx); p[n] = w; lsum += w; }
    red[tid] = lsum; __syncthreads();
    for (int s = 256; s; s >>= 1) { if (tid < s) red[tid] += red[tid + s]; __syncthreads(); }
    float inv = 1.0f / red[0]; __syncthreads();

    int d = tid & 127, grp = tid >> 7;        // 4 n-groups x 128 dims
    const float* Gn = g_G + (size_t)(hop + 1) * ROWS * Dd + (size_t)b * Nn * Dd;
    float du = 0.0f;
    for (int n = grp; n < Nn; n += 4) du += p[n] * Gn[(size_t)n * Dd + d];
    red[tid] = du; __syncthreads();
    if (grp == 0) {
        float tot = red[d] + red[128 + d] + red[256 + d] + red[384 + d];
        g_u[(size_t)b * Dd + d] += tot * inv;
    }
}

// ---------------- outputs: [sigmoid(logits) | u | logits] ----------------
__global__ void k_final(float* __restrict__ out) {
    int i = blockIdx.x * blockDim.x + threadIdx.x;
    if (i < ROWS) {
        float l = g_logits[i];
        out[i] = 1.0f / (1.0f + expf(-l));
        out[ROWS + Bq * Dd + i] = l;
    }
    if (i < Bq * Dd) out[ROWS + i] = g_u[i];
}

// ---------------- launch ----------------
extern "C" void kernel_launch(void* const* d_in, const int* in_sizes, int n_in,
                              void* d_out, int out_size) {
    const int*   story  = (const int*)d_in[0];
    const int*   kb     = (const int*)d_in[1];
    const int*   cv     = (const int*)d_in[2];
    const float* hidden = (const float*)d_in[3];
    const float* dh     = (const float*)d_in[4];
    const float* adj    = (const float*)d_in[5];
    const float* emb    = (const float*)d_in[6];
    const float* W      = (const float*)d_in[7];
    const float* a      = (const float*)d_in[8];
    float* out = (float*)d_out;

    k_build_nbr<<<2048, 256>>>(adj, kb, cv);
    k_init_u<<<8, 256>>>(hidden);

    for (int k = 0; k <= HOPSq; k++) {
        k_embed<<<2048, 256>>>(story, kb, cv, dh, emb, k);
        k_gemm_wh<<<dim3(256, 4), 256>>>(W, k);
        k_f1f2<<<8192, 256>>>(a, k);
        k_attn<<<2048, 256>>>(k);
    }
    for (int hop = 0; hop < HOPSq; hop++) {
        k_logits<<<2048, 256>>>(hop);
        k_softmax_update<<<16, 512>>>(hop);
    }
    k_final<<<(ROWS + 255) / 256, 256>>>(out);
}

// round 2
// speedup vs baseline: 2.1996x; 2.1996x over previous
#include <cuda_runtime.h>
#include <math.h>

#define Bq     16
#define Nn     1024
#define Dd     128
#define VOCABq 32000
#define HOPSq  3
#define HEADSq 4
#define KMAX   128
#define ALPHAq 0.2f
#define ROWS   (Bq * Nn)   // 16384
#define KTOT   512         // 4 heads * 128 (K-concat GEMM)

// ---------------- device scratch ----------------
__device__ int   g_nbr_idx[ROWS * KMAX];              // 8 MB
__device__ int   g_nbr_cnt[ROWS];
__device__ float g_X[ROWS * Dd];                      // 8 MB (reused per hop)
__device__ float g_wa1[16 * Dd];                      // (hop*4+h)*128
__device__ float g_wa2[16 * Dd];
__device__ float g_f1[HEADSq * ROWS];                 // reused per hop
__device__ float g_f2[HEADSq * ROWS];
__device__ float g_Y4[(HOPSq + 1) * ROWS * KTOT];     // 134 MB aggregated X per hop/head
__device__ float g_G[(HOPSq + 1) * ROWS * Dd];        // 33.5 MB
__device__ float g_u[Bq * Dd];
__device__ float g_logits[ROWS];

// ---------------- neighbor list (hop-invariant) ----------------
__global__ void k_build_nbr(const float* __restrict__ adj,
                            const int* __restrict__ kb_len,
                            const int* __restrict__ conv_len) {
    int warp = (blockIdx.x * blockDim.x + threadIdx.x) >> 5;
    int lane = threadIdx.x & 31;
    if (warp >= ROWS) return;
    int b = warp / Nn, n = warp % Nn;
    int ctx = kb_len[b] + conv_len[b];
    const float* arow = adj + (size_t)warp * Nn;
    int* idx = g_nbr_idx + (size_t)warp * KMAX;
    int cnt = 0;
    for (int m0 = 0; m0 < Nn; m0 += 32) {
        int m = m0 + lane;
        bool sel = (arow[m] > 0.0f) || (m == n && n >= ctx);
        unsigned bal = __ballot_sync(0xffffffffu, sel);
        if (sel) {
            int pos = cnt + __popc(bal & ((1u << lane) - 1u));
            if (pos < KMAX) idx[pos] = m;
        }
        cnt += __popc(bal);
    }
    if (lane == 0) g_nbr_cnt[warp] = cnt < KMAX ? cnt : KMAX;
}

// ---------------- wa = W @ a  (16 tiny projections) ----------------
__global__ void k_proj(const float* __restrict__ W_all, const float* __restrict__ a_all) {
    int hh = blockIdx.x;          // hop*4 + h, 0..15
    int d = threadIdx.x;          // 0..127
    const float* Wrow = W_all + ((size_t)hh * Dd + d) * Dd;
    const float* a = a_all + (size_t)hh * 2 * Dd;
    float s1 = 0.f, s2 = 0.f;
#pragma unroll 4
    for (int e = 0; e < Dd; e++) {
        float w = Wrow[e];
        s1 += w * a[e];
        s2 += w * a[Dd + e];
    }
    g_wa1[hh * Dd + d] = s1;
    g_wa2[hh * Dd + d] = s2;
}

// ---------------- embedding + LM add + fused f1/f2 ----------------
__global__ void k_embed_f(const int* __restrict__ story,
                          const int* __restrict__ kb_len,
                          const int* __restrict__ conv_len,
                          const float* __restrict__ dh,
                          const float* __restrict__ emb, int hop) {
    __shared__ float swa1[HEADSq * Dd];
    __shared__ float swa2[HEADSq * Dd];
    for (int t = threadIdx.x; t < HEADSq * Dd; t += blockDim.x) {
        swa1[t] = g_wa1[hop * HEADSq * Dd + t];
        swa2[t] = g_wa2[hop * HEADSq * Dd + t];
    }
    __syncthreads();
    int warp = (blockIdx.x * blockDim.x + threadIdx.x) >> 5;
    int lane = threadIdx.x & 31;
    if (warp >= ROWS) return;
    int b = warp / Nn, n = warp % Nn;
    const int* st = story + (size_t)warp * 4;
    int i0 = st[0], i1 = st[1], i2 = st[2], i3 = st[3];
    const float* E = emb + (size_t)hop * VOCABq * Dd;
    int d = lane * 4;
    float4 v0 = *(const float4*)(E + (size_t)i0 * Dd + d);
    float4 v1 = *(const float4*)(E + (size_t)i1 * Dd + d);
    float4 v2 = *(const float4*)(E + (size_t)i2 * Dd + d);
    float4 v3 = *(const float4*)(E + (size_t)i3 * Dd + d);
    float4 s;
    s.x = v0.x + v1.x + v2.x + v3.x;
    s.y = v0.y + v1.y + v2.y + v3.y;
    s.z = v0.z + v1.z + v2.z + v3.z;
    s.w = v0.w + v1.w + v2.w + v3.w;
    int rel = n - (kb_len[b] - 1);
    if (rel >= 0 && rel < conv_len[b]) {
        float4 g = *(const float4*)(dh + ((size_t)b * Nn + rel) * Dd + d);
        s.x += g.x; s.y += g.y; s.z += g.z; s.w += g.w;
    }
    *(float4*)(g_X + (size_t)warp * Dd + d) = s;

    // fused f1/f2: dot(X_row, wa1[h]), dot(X_row, wa2[h])
    float p1[HEADSq], p2[HEADSq];
#pragma unroll
    for (int h = 0; h < HEADSq; h++) {
        const float* w1 = swa1 + h * Dd + d;
        const float* w2 = swa2 + h * Dd + d;
        p1[h] = s.x * w1[0] + s.y * w1[1] + s.z * w1[2] + s.w * w1[3];
        p2[h] = s.x * w2[0] + s.y * w2[1] + s.z * w2[2] + s.w * w2[3];
    }
#pragma unroll
    for (int o = 16; o; o >>= 1)
#pragma unroll
        for (int h = 0; h < HEADSq; h++) {
            p1[h] += __shfl_xor_sync(0xffffffffu, p1[h], o);
            p2[h] += __shfl_xor_sync(0xffffffffu, p2[h], o);
        }
    if (lane == 0)
#pragma unroll
        for (int h = 0; h < HEADSq; h++) {
            g_f1[(size_t)h * ROWS + warp] = p1[h];
            g_f2[(size_t)h * ROWS + warp] = p2[h];
        }
}

// ---------------- sparse GAT attention: aggregate X -> Y4[hop] ----------------
__global__ void k_attn_agg(int hop) {
    __shared__ float sw[8][HEADSq][KMAX];   // 16 KB
    int wl = threadIdx.x >> 5;
    int warp = blockIdx.x * 8 + wl;
    int lane = threadIdx.x & 31;
    if (warp >= ROWS) return;
    int b = warp / Nn;
    int cnt = g_nbr_cnt[warp];
    const int* idx = g_nbr_idx + (size_t)warp * KMAX;
    int d = lane * 4;
    float* Y = g_Y4 + ((size_t)hop * ROWS + warp) * KTOT;
    float4 acc[HEADSq];
#pragma unroll
    for (int h = 0; h < HEADSq; h++) acc[h] = make_float4(0.f, 0.f, 0.f, 0.f);

    if (cnt == 0) {
        // softmax over all-NEG_INF -> uniform over all m; identical per head
        float4 a = make_float4(0.f, 0.f, 0.f, 0.f);
        for (int m = 0; m < Nn; m++) {
            float4 v = *(const float4*)(g_X + ((size_t)b * Nn + m) * Dd + d);
            a.x += v.x; a.y += v.y; a.z += v.z; a.w += v.w;
        }
        float sc = 1.0f / (float)Nn;
        a.x *= sc; a.y *= sc; a.z *= sc; a.w *= sc;
#pragma unroll
        for (int h = 0; h < HEADSq; h++) acc[h] = a;
    } else {
        float f1h[HEADSq];
#pragma unroll
        for (int h = 0; h < HEADSq; h++) f1h[h] = g_f1[(size_t)h * ROWS + warp];
        float mx[HEADSq];
#pragma unroll
        for (int h = 0; h < HEADSq; h++) mx[h] = -3.4e38f;
        for (int j = lane; j < cnt; j += 32) {
            int m = idx[j];
#pragma unroll
            for (int h = 0; h < HEADSq; h++) {
                float v = f1h[h] + g_f2[(size_t)h * ROWS + b * Nn + m];
                v = (v >= 0.0f) ? v : ALPHAq * v;
                sw[wl][h][j] = v;
                mx[h] = fmaxf(mx[h], v);
            }
        }
#pragma unroll
        for (int o = 16; o; o >>= 1)
#pragma unroll
            for (int h = 0; h < HEADSq; h++)
                mx[h] = fmaxf(mx[h], __shfl_xor_sync(0xffffffffu, mx[h], o));
        __syncwarp();
        float sum[HEADSq] = {0.f, 0.f, 0.f, 0.f};
        for (int j = lane; j < cnt; j += 32) {
#pragma unroll
            for (int h = 0; h < HEADSq; h++) {
                float w = expf(sw[wl][h][j] - mx[h]);
                sw[wl][h][j] = w;
                sum[h] += w;
            }
        }
#pragma unroll
        for (int o = 16; o; o >>= 1)
#pragma unroll
            for (int h = 0; h < HEADSq; h++)
                sum[h] += __shfl_xor_sync(0xffffffffu, sum[h], o);
        float sc[HEADSq];
#pragma unroll
        for (int h = 0; h < HEADSq; h++) sc[h] = 1.0f / sum[h];
        __syncwarp();
        for (int j = 0; j < cnt; j++) {
            int m = idx[j];
            float4 xv = *(const float4*)(g_X + ((size_t)b * Nn + m) * Dd + d);
#pragma unroll
            for (int h = 0; h < HEADSq; h++) {
                float w = sw[wl][h][j] * sc[h];
                acc[h].x += w * xv.x; acc[h].y += w * xv.y;
                acc[h].z += w * xv.z; acc[h].w += w * xv.w;
            }
        }
    }
#pragma unroll
    for (int h = 0; h < HEADSq; h++)
        *(float4*)(Y + h * Dd + d) = acc[h];
}

// ---------------- G[hop] = 0.25 * Y4[hop] (16384x512) @ W[hop] (512x128) ----------------
__global__ void __launch_bounds__(256, 2) k_gemm_G(const float* __restrict__ W_all) {
    __shared__ float As[2][16][132];
    __shared__ float Bs[2][16][128];
    int hop = blockIdx.y;
    int row0 = blockIdx.x * 128;
    const float* A = g_Y4 + (size_t)hop * ROWS * KTOT;
    const float* Bm = W_all + (size_t)hop * HEADSq * Dd * Dd;  // [512][128] contiguous
    int tid = threadIdx.x;
    int tx = tid & 15, ty = tid >> 4;

    int ar = tid >> 2;            // 0..63
    int akq = (tid & 3) * 4;      // 0,4,8,12
    int bkr = tid >> 5;           // 0..7
    int bc4 = (tid & 31) * 4;

    float4 pa0, pa1, pb0, pb1;
    pa0 = *(const float4*)(A + (size_t)(row0 + ar) * KTOT + akq);
    pa1 = *(const float4*)(A + (size_t)(row0 + ar + 64) * KTOT + akq);
    pb0 = *(const float4*)(Bm + (size_t)bkr * Dd + bc4);
    pb1 = *(const float4*)(Bm + (size_t)(bkr + 8) * Dd + bc4);
    As[0][akq + 0][ar] = pa0.x; As[0][akq + 1][ar] = pa0.y;
    As[0][akq + 2][ar] = pa0.z; As[0][akq + 3][ar] = pa0.w;
    As[0][akq + 0][ar + 64] = pa1.x; As[0][akq + 1][ar + 64] = pa1.y;
    As[0][akq + 2][ar + 64] = pa1.z; As[0][akq + 3][ar + 64] = pa1.w;
    *(float4*)&Bs[0][bkr][bc4] = pb0;
    *(float4*)&Bs[0][bkr + 8][bc4] = pb1;
    __syncthreads();

    float acc[8][8];
#pragma unroll
    for (int r = 0; r < 8; r++)
#pragma unroll
        for (int c = 0; c < 8; c++) acc[r][c] = 0.0f;

    int buf = 0;
    for (int kt = 0; kt < 32; ++kt) {
        if (kt < 31) {
            int k0 = (kt + 1) * 16;
            pa0 = *(const float4*)(A + (size_t)(row0 + ar) * KTOT + k0 + akq);
            pa1 = *(const float4*)(A + (size_t)(row0 + ar + 64) * KTOT + k0 + akq);
            pb0 = *(const float4*)(Bm + (size_t)(k0 + bkr) * Dd + bc4);
            pb1 = *(const float4*)(Bm + (size_t)(k0 + bkr + 8) * Dd + bc4);
        }
#pragma unroll
        for (int kk = 0; kk < 16; ++kk) {
            float4 a0 = *(const float4*)&As[buf][kk][ty * 4];
            float4 a1 = *(const float4*)&As[buf][kk][64 + ty * 4];
            float4 b0 = *(const float4*)&Bs[buf][kk][tx * 4];
            float4 b1 = *(const float4*)&Bs[buf][kk][64 + tx * 4];
            float av[8] = {a0.x, a0.y, a0.z, a0.w, a1.x, a1.y, a1.z, a1.w};
            float bv[8] = {b0.x, b0.y, b0.z, b0.w, b1.x, b1.y, b1.z, b1.w};
#pragma unroll
            for (int r = 0; r < 8; r++)
#pragma unroll
                for (int c = 0; c < 8; c++) acc[r][c] += av[r] * bv[c];
        }
        if (kt < 31) {
            int nb = buf ^ 1;
            As[nb][akq + 0][ar] = pa0.x; As[nb][akq + 1][ar] = pa0.y;
            As[nb][akq + 2][ar] = pa0.z; As[nb][akq + 3][ar] = pa0.w;
            As[nb][akq + 0][ar + 64] = pa1.x; As[nb][akq + 1][ar + 64] = pa1.y;
            As[nb][akq + 2][ar + 64] = pa1.z; As[nb][akq + 3][ar + 64] = pa1.w;
            *(float4*)&Bs[nb][bkr][bc4] = pb0;
            *(float4*)&Bs[nb][bkr + 8][bc4] = pb1;
            __syncthreads();
            buf = nb;
        }
    }

    float* G = g_G + ((size_t)hop * ROWS + row0) * Dd;
#pragma unroll
    for (int r = 0; r < 8; r++) {
        int grow = (r < 4) ? (ty * 4 + r) : (64 + ty * 4 + (r - 4));
        float4 o0 = make_float4(acc[r][0] * 0.25f, acc[r][1] * 0.25f,
                                acc[r][2] * 0.25f, acc[r][3] * 0.25f);
        float4 o1 = make_float4(acc[r][4] * 0.25f, acc[r][5] * 0.25f,
                                acc[r][6] * 0.25f, acc[r][7] * 0.25f);
        *(float4*)(G + (size_t)grow * Dd + tx * 4) = o0;
        *(float4*)(G + (size_t)grow * Dd + 64 + tx * 4) = o1;
    }
}

// ---------------- hop recurrence ----------------
__global__ void k_init_u(const float* __restrict__ hidden) {
    int i = blockIdx.x * blockDim.x + threadIdx.x;
    if (i < Bq * Dd) g_u[i] = hidden[i];
}

__global__ void k_logits(int hop) {
    int warp = (blockIdx.x * blockDim.x + threadIdx.x) >> 5;
    int lane = threadIdx.x & 31;
    if (warp >= ROWS) return;
    int b = warp / Nn;
    int d = lane * 4;
    float4 g = *(const float4*)(g_G + ((size_t)hop * ROWS + warp) * Dd + d);
    float4 u = *(const float4*)(g_u + (size_t)b * Dd + d);
    float s = g.x * u.x + g.y * u.y + g.z * u.z + g.w * u.w;
#pragma unroll
    for (int o = 16; o; o >>= 1) s += __shfl_xor_sync(0xffffffffu, s, o);
    if (lane == 0) g_logits[warp] = s;
}

__global__ void k_softmax_update(int hop) {   // uses G[hop+1]
    int b = blockIdx.x;
    int tid = threadIdx.x;                    // 512 threads
    __shared__ float red[512];
    __shared__ float p[Nn];
    const float* lg = g_logits + (size_t)b * Nn;

    float lmax = -3.4e38f;
    for (int n = tid; n < Nn; n += 512) lmax = fmaxf(lmax, lg[n]);
    red[tid] = lmax; __syncthreads();
    for (int s = 256; s; s >>= 1) { if (tid < s) red[tid] = fmaxf(red[tid], red[tid + s]); __syncthreads(); }
    float mx = red[0]; __syncthreads();

    float lsum = 0.0f;
    for (int n = tid; n < Nn; n += 512) { float w = expf(lg[n] - mx); p[n] = w; lsum += w; }
    red[tid] = lsum; __syncthreads();
    for (int s = 256; s; s >>= 1) { if (tid < s) red[tid] += red[tid + s]; __syncthreads(); }
    float inv = 1.0f / red[0]; __syncthreads();

    int d = tid & 127, grp = tid >> 7;
    const float* Gn = g_G + (size_t)(hop + 1) * ROWS * Dd + (size_t)b * Nn * Dd;
    float du = 0.0f;
    for (int n = grp; n < Nn; n += 4) du += p[n] * Gn[(size_t)n * Dd + d];
    red[tid] = du; __syncthreads();
    if (grp == 0) {
        float tot = red[d] + red[128 + d] + red[256 + d] + red[384 + d];
        g_u[(size_t)b * Dd + d] += tot * inv;
    }
}

// ---------------- outputs: [sigmoid(logits) | u | logits] ----------------
__global__ void k_final(float* __restrict__ out) {
    int i = blockIdx.x * blockDim.x + threadIdx.x;
    if (i < ROWS) {
        float l = g_logits[i];
        out[i] = 1.0f / (1.0f + expf(-l));
        out[ROWS + Bq * Dd + i] = l;
    }
    if (i < Bq * Dd) out[ROWS + i] = g_u[i];
}

// ---------------- launch ----------------
extern "C" void kernel_launch(void* const* d_in, const int* in_sizes, int n_in,
                              void* d_out, int out_size) {
    const int*   story  = (const int*)d_in[0];
    const int*   kb     = (const int*)d_in[1];
    const int*   cv     = (const int*)d_in[2];
    const float* hidden = (const float*)d_in[3];
    const float* dh     = (const float*)d_in[4];
    const float* adj    = (const float*)d_in[5];
    const float* emb    = (const float*)d_in[6];
    const float* W      = (const float*)d_in[7];
    const float* a      = (const float*)d_in[8];
    float* out = (float*)d_out;

    k_build_nbr<<<2048, 256>>>(adj, kb, cv);
    k_init_u<<<8, 256>>>(hidden);
    k_proj<<<16, 128>>>(W, a);

    for (int k = 0; k <= HOPSq; k++) {
        k_embed_f<<<2048, 256>>>(story, kb, cv, dh, emb, k);
        k_attn_agg<<<2048, 256>>>(k);
    }
    k_gemm_G<<<dim3(128, 4), 256>>>(W);

    for (int hop = 0; hop < HOPSq; hop++) {
        k_logits<<<2048, 256>>>(hop);
        k_softmax_update<<<16, 512>>>(hop);
    }
    k_final<<<(ROWS + 255) / 256, 256>>>(out);
}